// round 1
// baseline (speedup 1.0000x reference)
#include <cuda_runtime.h>

// Problem: 2 inputs, each 32*3*512*512 = 25165824 fp32. Output: 1 fp32 scalar.
// total_loss = 0.5*(0.5*mae_thr + 0.5*mse_thr) + 0.5*(0.5*mae + 0.5*mse)

#define N_ELEMS   25165824
#define N_VEC4    (N_ELEMS / 4)
#define BLOCKS    1184        // 148 SMs * 8
#define THREADS   256

// Device-global accumulators (no cudaMalloc allowed)
__device__ double g_sum_abs;
__device__ double g_sum_sq;
__device__ double g_mae;       // mean |d|
__device__ double g_mse;       // mean d^2
__device__ double g_sum_abs_thr;
__device__ double g_sum_sq_thr;
__device__ unsigned long long g_cnt_abs;
__device__ unsigned long long g_cnt_sq;

__global__ void zero_kernel() {
    g_sum_abs = 0.0; g_sum_sq = 0.0;
    g_sum_abs_thr = 0.0; g_sum_sq_thr = 0.0;
    g_cnt_abs = 0ULL; g_cnt_sq = 0ULL;
}

__device__ __forceinline__ double warp_reduce(double v) {
    #pragma unroll
    for (int o = 16; o > 0; o >>= 1)
        v += __shfl_down_sync(0xFFFFFFFFu, v, o);
    return v;
}

__device__ __forceinline__ unsigned warp_reduce_u(unsigned v) {
    #pragma unroll
    for (int o = 16; o > 0; o >>= 1)
        v += __shfl_down_sync(0xFFFFFFFFu, v, o);
    return v;
}

// ---------- Pass 1: sum |d| and d^2 ----------
__global__ void __launch_bounds__(THREADS)
pass1_kernel(const float4* __restrict__ a, const float4* __restrict__ b) {
    double s_abs = 0.0, s_sq = 0.0;
    int stride = gridDim.x * blockDim.x;
    for (int i = blockIdx.x * blockDim.x + threadIdx.x; i < N_VEC4; i += stride) {
        float4 x = __ldg(a + i);
        float4 y = __ldg(b + i);
        float d0 = x.x - y.x, d1 = x.y - y.y, d2 = x.z - y.z, d3 = x.w - y.w;
        // accumulate in float per-vector, promote to double per-iteration
        float fa = fabsf(d0) + fabsf(d1) + fabsf(d2) + fabsf(d3);
        float fs = d0*d0 + d1*d1 + d2*d2 + d3*d3;
        s_abs += (double)fa;
        s_sq  += (double)fs;
    }
    // block reduce
    __shared__ double sh_abs[THREADS / 32];
    __shared__ double sh_sq[THREADS / 32];
    int lane = threadIdx.x & 31, wid = threadIdx.x >> 5;
    s_abs = warp_reduce(s_abs);
    s_sq  = warp_reduce(s_sq);
    if (lane == 0) { sh_abs[wid] = s_abs; sh_sq[wid] = s_sq; }
    __syncthreads();
    if (wid == 0) {
        s_abs = (lane < THREADS / 32) ? sh_abs[lane] : 0.0;
        s_sq  = (lane < THREADS / 32) ? sh_sq[lane]  : 0.0;
        s_abs = warp_reduce(s_abs);
        s_sq  = warp_reduce(s_sq);
        if (lane == 0) {
            atomicAdd(&g_sum_abs, s_abs);
            atomicAdd(&g_sum_sq,  s_sq);
        }
    }
}

// ---------- compute means ----------
__global__ void means_kernel() {
    g_mae = g_sum_abs / (double)N_ELEMS;
    g_mse = g_sum_sq  / (double)N_ELEMS;
}

// ---------- Pass 2: thresholded sums + counts ----------
__global__ void __launch_bounds__(THREADS)
pass2_kernel(const float4* __restrict__ a, const float4* __restrict__ b) {
    float mae_t = (float)g_mae;
    float mse_t = (float)g_mse;
    double s_abs = 0.0, s_sq = 0.0;
    unsigned c_abs = 0, c_sq = 0;
    int stride = gridDim.x * blockDim.x;
    for (int i = blockIdx.x * blockDim.x + threadIdx.x; i < N_VEC4; i += stride) {
        float4 x = __ldg(a + i);
        float4 y = __ldg(b + i);
        float d[4] = {x.x - y.x, x.y - y.y, x.z - y.z, x.w - y.w};
        float fa = 0.0f, fs = 0.0f;
        #pragma unroll
        for (int k = 0; k < 4; k++) {
            float ad = fabsf(d[k]);
            float sq = d[k] * d[k];
            if (ad >= mae_t) { fa += ad; c_abs++; }
            if (sq >= mse_t) { fs += sq; c_sq++; }
        }
        s_abs += (double)fa;
        s_sq  += (double)fs;
    }
    __shared__ double sh_abs[THREADS / 32];
    __shared__ double sh_sq[THREADS / 32];
    __shared__ unsigned sh_ca[THREADS / 32];
    __shared__ unsigned sh_cs[THREADS / 32];
    int lane = threadIdx.x & 31, wid = threadIdx.x >> 5;
    s_abs = warp_reduce(s_abs);
    s_sq  = warp_reduce(s_sq);
    c_abs = warp_reduce_u(c_abs);
    c_sq  = warp_reduce_u(c_sq);
    if (lane == 0) { sh_abs[wid] = s_abs; sh_sq[wid] = s_sq; sh_ca[wid] = c_abs; sh_cs[wid] = c_sq; }
    __syncthreads();
    if (wid == 0) {
        bool ok = lane < THREADS / 32;
        s_abs = ok ? sh_abs[lane] : 0.0;
        s_sq  = ok ? sh_sq[lane]  : 0.0;
        c_abs = ok ? sh_ca[lane]  : 0u;
        c_sq  = ok ? sh_cs[lane]  : 0u;
        s_abs = warp_reduce(s_abs);
        s_sq  = warp_reduce(s_sq);
        c_abs = warp_reduce_u(c_abs);
        c_sq  = warp_reduce_u(c_sq);
        if (lane == 0) {
            atomicAdd(&g_sum_abs_thr, s_abs);
            atomicAdd(&g_sum_sq_thr,  s_sq);
            atomicAdd(&g_cnt_abs, (unsigned long long)c_abs);
            atomicAdd(&g_cnt_sq,  (unsigned long long)c_sq);
        }
    }
}

// ---------- finalize ----------
__global__ void final_kernel(float* __restrict__ out) {
    double mae = g_mae;
    double mse = g_mse;
    double mae_thr = (g_cnt_abs > 0) ? g_sum_abs_thr / (double)g_cnt_abs : 0.0;
    double mse_thr = (g_cnt_sq  > 0) ? g_sum_sq_thr  / (double)g_cnt_sq  : 0.0;
    double combined_thr     = 0.5 * mae_thr + 0.5 * mse_thr;
    double combined_non_thr = 0.5 * mae     + 0.5 * mse;
    double total = 0.5 * combined_thr + 0.5 * combined_non_thr;
    out[0] = (float)total;
}

extern "C" void kernel_launch(void* const* d_in, const int* in_sizes, int n_in,
                              void* d_out, int out_size) {
    const float4* a = (const float4*)d_in[0];
    const float4* b = (const float4*)d_in[1];
    float* out = (float*)d_out;

    zero_kernel<<<1, 1>>>();
    pass1_kernel<<<BLOCKS, THREADS>>>(a, b);
    means_kernel<<<1, 1>>>();
    pass2_kernel<<<BLOCKS, THREADS>>>(a, b);
    final_kernel<<<1, 1>>>(out);
}

// round 2
// speedup vs baseline: 1.5866x; 1.5866x over previous
#include <cuda_runtime.h>
#include <cuda_fp16.h>

// total_loss = 0.5*(0.5*mae_thr + 0.5*mse_thr) + 0.5*(0.5*mae + 0.5*mse)
// N = 32*3*512*512 = 25165824 fp32 per input.

#define N_ELEMS   25165824
#define N_VEC4    6291456      // N/4   (float4 chunks)
#define N_VEC8H   3145728      // N/8   (8-half = 16B chunks)
#define BLOCKS    1184         // 148 SMs * 8
#define THREADS   256
#define TOT       (BLOCKS * THREADS)   // 303104
#define P1_ITERS  20           // N_VEC4  = TOT*20 + 229376
#define P1_REM    229376
#define P2_ITERS  10           // N_VEC8H = TOT*10 + 114688
#define P2_REM    114688

// ---- static device scratch (no runtime allocation allowed) ----
__device__ __half  g_absdiff[N_ELEMS];          // 50.3 MB |d| in fp16
__device__ double  g_p1_abs[BLOCKS];
__device__ double  g_p1_sq [BLOCKS];
__device__ double  g_p2_abs[BLOCKS];
__device__ double  g_p2_sq [BLOCKS];
__device__ unsigned g_p2_ca[BLOCKS];
__device__ unsigned g_p2_cs[BLOCKS];
__device__ float   g_mae_f, g_mse_f;
__device__ double  g_mae_d, g_mse_d;

__device__ __forceinline__ double wred_d(double v) {
    #pragma unroll
    for (int o = 16; o > 0; o >>= 1) v += __shfl_down_sync(0xFFFFFFFFu, v, o);
    return v;
}
__device__ __forceinline__ unsigned wred_u(unsigned v) {
    #pragma unroll
    for (int o = 16; o > 0; o >>= 1) v += __shfl_down_sync(0xFFFFFFFFu, v, o);
    return v;
}

// ---------------- Pass 1: sums of |d|, d^2 ; write |d| as fp16 ----------------
__global__ void __launch_bounds__(THREADS)
pass1_kernel(const float4* __restrict__ a, const float4* __restrict__ b) {
    const int tid = blockIdx.x * THREADS + threadIdx.x;
    uint2* __restrict__ outp = reinterpret_cast<uint2*>(g_absdiff);  // 4 halfs per uint2
    double d_abs = 0.0, d_sq = 0.0;

    #pragma unroll
    for (int outer = 0; outer < 5; outer++) {
        const int base = tid + outer * 4 * TOT;
        float4 xa[4], xb[4];
        #pragma unroll
        for (int k = 0; k < 4; k++) { xa[k] = a[base + k * TOT]; xb[k] = b[base + k * TOT]; }
        float fa = 0.0f, fs = 0.0f;
        #pragma unroll
        for (int k = 0; k < 4; k++) {
            float d0 = xa[k].x - xb[k].x, d1 = xa[k].y - xb[k].y;
            float d2 = xa[k].z - xb[k].z, d3 = xa[k].w - xb[k].w;
            float a0 = fabsf(d0), a1 = fabsf(d1), a2 = fabsf(d2), a3 = fabsf(d3);
            fa += (a0 + a1) + (a2 + a3);
            fs += (d0*d0 + d1*d1) + (d2*d2 + d3*d3);
            __half2 h01 = __floats2half2_rn(a0, a1);
            __half2 h23 = __floats2half2_rn(a2, a3);
            uint2 pk;
            pk.x = reinterpret_cast<unsigned&>(h01);
            pk.y = reinterpret_cast<unsigned&>(h23);
            outp[base + k * TOT] = pk;
        }
        d_abs += (double)fa; d_sq += (double)fs;
    }
    if (tid < P1_REM) {
        const int idx = tid + P1_ITERS * TOT;
        float4 xa = a[idx], xb = b[idx];
        float d0 = xa.x - xb.x, d1 = xa.y - xb.y, d2 = xa.z - xb.z, d3 = xa.w - xb.w;
        float a0 = fabsf(d0), a1 = fabsf(d1), a2 = fabsf(d2), a3 = fabsf(d3);
        d_abs += (double)((a0 + a1) + (a2 + a3));
        d_sq  += (double)((d0*d0 + d1*d1) + (d2*d2 + d3*d3));
        __half2 h01 = __floats2half2_rn(a0, a1);
        __half2 h23 = __floats2half2_rn(a2, a3);
        uint2 pk;
        pk.x = reinterpret_cast<unsigned&>(h01);
        pk.y = reinterpret_cast<unsigned&>(h23);
        outp[idx] = pk;
    }

    // block reduce (double)
    __shared__ double sh_a[THREADS / 32], sh_s[THREADS / 32];
    int lane = threadIdx.x & 31, wid = threadIdx.x >> 5;
    d_abs = wred_d(d_abs); d_sq = wred_d(d_sq);
    if (lane == 0) { sh_a[wid] = d_abs; sh_s[wid] = d_sq; }
    __syncthreads();
    if (wid == 0) {
        bool ok = lane < THREADS / 32;
        d_abs = ok ? sh_a[lane] : 0.0;
        d_sq  = ok ? sh_s[lane] : 0.0;
        d_abs = wred_d(d_abs); d_sq = wred_d(d_sq);
        if (lane == 0) { g_p1_abs[blockIdx.x] = d_abs; g_p1_sq[blockIdx.x] = d_sq; }
    }
}

// ---------------- reduce partials -> means ----------------
__global__ void __launch_bounds__(1024)
means_kernel() {
    double va = 0.0, vs = 0.0;
    for (int i = threadIdx.x; i < BLOCKS; i += 1024) { va += g_p1_abs[i]; vs += g_p1_sq[i]; }
    __shared__ double sh_a[32], sh_s[32];
    int lane = threadIdx.x & 31, wid = threadIdx.x >> 5;
    va = wred_d(va); vs = wred_d(vs);
    if (lane == 0) { sh_a[wid] = va; sh_s[wid] = vs; }
    __syncthreads();
    if (wid == 0) {
        va = (lane < 32) ? sh_a[lane] : 0.0;
        vs = (lane < 32) ? sh_s[lane] : 0.0;
        va = wred_d(va); vs = wred_d(vs);
        if (lane == 0) {
            double mae = va / (double)N_ELEMS;
            double mse = vs / (double)N_ELEMS;
            g_mae_d = mae; g_mse_d = mse;
            g_mae_f = (float)mae; g_mse_f = (float)mse;
        }
    }
}

// ---------------- Pass 2: thresholded sums + counts over fp16 |d| ----------------
__global__ void __launch_bounds__(THREADS)
pass2_kernel() {
    const float mae_t = g_mae_f;
    const float mse_t = g_mse_f;
    const int tid = blockIdx.x * THREADS + threadIdx.x;
    const uint4* __restrict__ in = reinterpret_cast<const uint4*>(g_absdiff); // 8 halfs
    double d_abs = 0.0, d_sq = 0.0;
    unsigned ca = 0, cs = 0;

    #pragma unroll
    for (int outer = 0; outer < 2; outer++) {
        const int base = tid + outer * 5 * TOT;
        uint4 v[5];
        #pragma unroll
        for (int k = 0; k < 5; k++) v[k] = in[base + k * TOT];
        float fa = 0.0f, fs = 0.0f;
        #pragma unroll
        for (int k = 0; k < 5; k++) {
            unsigned w[4] = {v[k].x, v[k].y, v[k].z, v[k].w};
            #pragma unroll
            for (int j = 0; j < 4; j++) {
                __half2 h = reinterpret_cast<__half2&>(w[j]);
                float2 f = __half22float2(h);
                float vv0 = f.x * f.x, vv1 = f.y * f.y;
                if (f.x >= mae_t) { fa += f.x; ca++; }
                if (f.y >= mae_t) { fa += f.y; ca++; }
                if (vv0 >= mse_t) { fs += vv0; cs++; }
                if (vv1 >= mse_t) { fs += vv1; cs++; }
            }
        }
        d_abs += (double)fa; d_sq += (double)fs;
    }
    if (tid < P2_REM) {
        uint4 v = in[tid + P2_ITERS * TOT];
        unsigned w[4] = {v.x, v.y, v.z, v.w};
        float fa = 0.0f, fs = 0.0f;
        #pragma unroll
        for (int j = 0; j < 4; j++) {
            __half2 h = reinterpret_cast<__half2&>(w[j]);
            float2 f = __half22float2(h);
            float vv0 = f.x * f.x, vv1 = f.y * f.y;
            if (f.x >= mae_t) { fa += f.x; ca++; }
            if (f.y >= mae_t) { fa += f.y; ca++; }
            if (vv0 >= mse_t) { fs += vv0; cs++; }
            if (vv1 >= mse_t) { fs += vv1; cs++; }
        }
        d_abs += (double)fa; d_sq += (double)fs;
    }

    __shared__ double   sh_a[THREADS / 32], sh_s[THREADS / 32];
    __shared__ unsigned sh_ca[THREADS / 32], sh_cs[THREADS / 32];
    int lane = threadIdx.x & 31, wid = threadIdx.x >> 5;
    d_abs = wred_d(d_abs); d_sq = wred_d(d_sq);
    ca = wred_u(ca); cs = wred_u(cs);
    if (lane == 0) { sh_a[wid] = d_abs; sh_s[wid] = d_sq; sh_ca[wid] = ca; sh_cs[wid] = cs; }
    __syncthreads();
    if (wid == 0) {
        bool ok = lane < THREADS / 32;
        d_abs = ok ? sh_a[lane] : 0.0;
        d_sq  = ok ? sh_s[lane] : 0.0;
        ca    = ok ? sh_ca[lane] : 0u;
        cs    = ok ? sh_cs[lane] : 0u;
        d_abs = wred_d(d_abs); d_sq = wred_d(d_sq);
        ca = wred_u(ca); cs = wred_u(cs);
        if (lane == 0) {
            g_p2_abs[blockIdx.x] = d_abs; g_p2_sq[blockIdx.x] = d_sq;
            g_p2_ca[blockIdx.x]  = ca;    g_p2_cs[blockIdx.x]  = cs;
        }
    }
}

// ---------------- finalize ----------------
__global__ void __launch_bounds__(1024)
final_kernel(float* __restrict__ out) {
    double va = 0.0, vs = 0.0;
    unsigned long long ca = 0, cs = 0;
    for (int i = threadIdx.x; i < BLOCKS; i += 1024) {
        va += g_p2_abs[i]; vs += g_p2_sq[i];
        ca += g_p2_ca[i];  cs += g_p2_cs[i];
    }
    __shared__ double sh_a[32], sh_s[32];
    __shared__ unsigned long long sh_ca[32], sh_cs[32];
    int lane = threadIdx.x & 31, wid = threadIdx.x >> 5;
    va = wred_d(va); vs = wred_d(vs);
    #pragma unroll
    for (int o = 16; o > 0; o >>= 1) {
        ca += __shfl_down_sync(0xFFFFFFFFu, ca, o);
        cs += __shfl_down_sync(0xFFFFFFFFu, cs, o);
    }
    if (lane == 0) { sh_a[wid] = va; sh_s[wid] = vs; sh_ca[wid] = ca; sh_cs[wid] = cs; }
    __syncthreads();
    if (wid == 0) {
        va = (lane < 32) ? sh_a[lane] : 0.0;
        vs = (lane < 32) ? sh_s[lane] : 0.0;
        ca = (lane < 32) ? sh_ca[lane] : 0ULL;
        cs = (lane < 32) ? sh_cs[lane] : 0ULL;
        va = wred_d(va); vs = wred_d(vs);
        #pragma unroll
        for (int o = 16; o > 0; o >>= 1) {
            ca += __shfl_down_sync(0xFFFFFFFFu, ca, o);
            cs += __shfl_down_sync(0xFFFFFFFFu, cs, o);
        }
        if (lane == 0) {
            double mae = g_mae_d, mse = g_mse_d;
            double mae_thr = (ca > 0) ? va / (double)ca : 0.0;
            double mse_thr = (cs > 0) ? vs / (double)cs : 0.0;
            double total = 0.5 * (0.5 * mae_thr + 0.5 * mse_thr)
                         + 0.5 * (0.5 * mae     + 0.5 * mse);
            out[0] = (float)total;
        }
    }
}

extern "C" void kernel_launch(void* const* d_in, const int* in_sizes, int n_in,
                              void* d_out, int out_size) {
    const float4* a = (const float4*)d_in[0];
    const float4* b = (const float4*)d_in[1];
    float* out = (float*)d_out;

    pass1_kernel<<<BLOCKS, THREADS>>>(a, b);
    means_kernel<<<1, 1024>>>();
    pass2_kernel<<<BLOCKS, THREADS>>>();
    final_kernel<<<1, 1024>>>(out);
}

// round 4
// speedup vs baseline: 1.8175x; 1.1455x over previous
#include <cuda_runtime.h>
#include <cuda_fp16.h>

// total_loss = 0.5*(0.5*mae_thr + 0.5*mse_thr) + 0.5*(0.5*mae + 0.5*mse)
// N = 32*3*512*512 = 25165824 fp32 per input.

#define N_ELEMS   25165824
#define BLOCKS    1184         // 148 SMs * 8
#define THREADS   256
#define TOT       (BLOCKS * THREADS)   // 303104
#define P1_ITERS  20           // N/4  = TOT*20 + 229376
#define P1_REM    229376
#define P2_ITERS  10           // N/8  = TOT*10 + 114688
#define P2_REM    114688

// ---- static device scratch (no runtime allocation allowed) ----
__device__ __half  g_absdiff[N_ELEMS];          // 50.3 MB |d| in fp16
__device__ double  g_sum_abs, g_sum_sq;         // pass1 totals (atomics)
__device__ double  g_thr_abs, g_thr_sq;         // pass2 totals (atomics)
__device__ unsigned long long g_cnt_abs, g_cnt_sq;

__device__ __forceinline__ double wred_d(double v) {
    #pragma unroll
    for (int o = 16; o > 0; o >>= 1) v += __shfl_down_sync(0xFFFFFFFFu, v, o);
    return v;
}
__device__ __forceinline__ unsigned wred_u(unsigned v) {
    #pragma unroll
    for (int o = 16; o > 0; o >>= 1) v += __shfl_down_sync(0xFFFFFFFFu, v, o);
    return v;
}

__global__ void zero_kernel() {
    g_sum_abs = 0.0; g_sum_sq = 0.0;
    g_thr_abs = 0.0; g_thr_sq = 0.0;
    g_cnt_abs = 0ULL; g_cnt_sq = 0ULL;
}

// ---------------- Pass 1: sums of |d|, d^2 ; write |d| as fp16 ----------------
__global__ void __launch_bounds__(THREADS)
pass1_kernel(const float4* __restrict__ a, const float4* __restrict__ b) {
    const int tid = blockIdx.x * THREADS + threadIdx.x;
    uint2* __restrict__ outp = reinterpret_cast<uint2*>(g_absdiff);  // 4 halfs per uint2
    double d_abs = 0.0, d_sq = 0.0;

    #pragma unroll
    for (int outer = 0; outer < 5; outer++) {
        const int base = tid + outer * 4 * TOT;
        float4 xa[4], xb[4];
        #pragma unroll
        for (int k = 0; k < 4; k++) { xa[k] = a[base + k * TOT]; xb[k] = b[base + k * TOT]; }
        float fa = 0.0f, fs = 0.0f;
        #pragma unroll
        for (int k = 0; k < 4; k++) {
            float d0 = xa[k].x - xb[k].x, d1 = xa[k].y - xb[k].y;
            float d2 = xa[k].z - xb[k].z, d3 = xa[k].w - xb[k].w;
            float a0 = fabsf(d0), a1 = fabsf(d1), a2 = fabsf(d2), a3 = fabsf(d3);
            fa += (a0 + a1) + (a2 + a3);
            fs += (d0*d0 + d1*d1) + (d2*d2 + d3*d3);
            __half2 h01 = __floats2half2_rn(a0, a1);
            __half2 h23 = __floats2half2_rn(a2, a3);
            uint2 pk;
            pk.x = reinterpret_cast<unsigned&>(h01);
            pk.y = reinterpret_cast<unsigned&>(h23);
            outp[base + k * TOT] = pk;
        }
        d_abs += (double)fa; d_sq += (double)fs;
    }
    if (tid < P1_REM) {
        const int idx = tid + P1_ITERS * TOT;
        float4 xa = a[idx], xb = b[idx];
        float d0 = xa.x - xb.x, d1 = xa.y - xb.y, d2 = xa.z - xb.z, d3 = xa.w - xb.w;
        float a0 = fabsf(d0), a1 = fabsf(d1), a2 = fabsf(d2), a3 = fabsf(d3);
        d_abs += (double)((a0 + a1) + (a2 + a3));
        d_sq  += (double)((d0*d0 + d1*d1) + (d2*d2 + d3*d3));
        __half2 h01 = __floats2half2_rn(a0, a1);
        __half2 h23 = __floats2half2_rn(a2, a3);
        uint2 pk;
        pk.x = reinterpret_cast<unsigned&>(h01);
        pk.y = reinterpret_cast<unsigned&>(h23);
        outp[idx] = pk;
    }

    // block reduce (double) -> 2 atomics per block
    __shared__ double sh_a[THREADS / 32], sh_s[THREADS / 32];
    int lane = threadIdx.x & 31, wid = threadIdx.x >> 5;
    d_abs = wred_d(d_abs); d_sq = wred_d(d_sq);
    if (lane == 0) { sh_a[wid] = d_abs; sh_s[wid] = d_sq; }
    __syncthreads();
    if (wid == 0) {
        bool ok = lane < THREADS / 32;
        d_abs = ok ? sh_a[lane] : 0.0;
        d_sq  = ok ? sh_s[lane] : 0.0;
        d_abs = wred_d(d_abs); d_sq = wred_d(d_sq);
        if (lane == 0) {
            atomicAdd(&g_sum_abs, d_abs);
            atomicAdd(&g_sum_sq,  d_sq);
        }
    }
}

// ---------------- Pass 2: thresholded sums + counts over fp16 |d| ----------------
__global__ void __launch_bounds__(THREADS)
pass2_kernel() {
    // thresholds from pass1 totals (stream-ordered, visible)
    const float mae_t = (float)(g_sum_abs * (1.0 / (double)N_ELEMS));
    const float mse_t = (float)(g_sum_sq  * (1.0 / (double)N_ELEMS));
    const int tid = blockIdx.x * THREADS + threadIdx.x;
    const uint4* __restrict__ in = reinterpret_cast<const uint4*>(g_absdiff); // 8 halfs
    double d_abs = 0.0, d_sq = 0.0;
    unsigned ca = 0, cs = 0;

    #pragma unroll
    for (int outer = 0; outer < 2; outer++) {
        const int base = tid + outer * 5 * TOT;
        uint4 v[5];
        #pragma unroll
        for (int k = 0; k < 5; k++) v[k] = in[base + k * TOT];
        float fa = 0.0f, fs = 0.0f;
        #pragma unroll
        for (int k = 0; k < 5; k++) {
            unsigned w[4] = {v[k].x, v[k].y, v[k].z, v[k].w};
            #pragma unroll
            for (int j = 0; j < 4; j++) {
                __half2 h = reinterpret_cast<__half2&>(w[j]);
                float2 f = __half22float2(h);
                float vv0 = f.x * f.x, vv1 = f.y * f.y;
                if (f.x >= mae_t) { fa += f.x; ca++; }
                if (f.y >= mae_t) { fa += f.y; ca++; }
                if (vv0 >= mse_t) { fs += vv0; cs++; }
                if (vv1 >= mse_t) { fs += vv1; cs++; }
            }
        }
        d_abs += (double)fa; d_sq += (double)fs;
    }
    if (tid < P2_REM) {
        uint4 v = in[tid + P2_ITERS * TOT];
        unsigned w[4] = {v.x, v.y, v.z, v.w};
        float fa = 0.0f, fs = 0.0f;
        #pragma unroll
        for (int j = 0; j < 4; j++) {
            __half2 h = reinterpret_cast<__half2&>(w[j]);
            float2 f = __half22float2(h);
            float vv0 = f.x * f.x, vv1 = f.y * f.y;
            if (f.x >= mae_t) { fa += f.x; ca++; }
            if (f.y >= mae_t) { fa += f.y; ca++; }
            if (vv0 >= mse_t) { fs += vv0; cs++; }
            if (vv1 >= mse_t) { fs += vv1; cs++; }
        }
        d_abs += (double)fa; d_sq += (double)fs;
    }

    __shared__ double   sh_a[THREADS / 32], sh_s[THREADS / 32];
    __shared__ unsigned sh_ca[THREADS / 32], sh_cs[THREADS / 32];
    int lane = threadIdx.x & 31, wid = threadIdx.x >> 5;
    d_abs = wred_d(d_abs); d_sq = wred_d(d_sq);
    ca = wred_u(ca); cs = wred_u(cs);
    if (lane == 0) { sh_a[wid] = d_abs; sh_s[wid] = d_sq; sh_ca[wid] = ca; sh_cs[wid] = cs; }
    __syncthreads();
    if (wid == 0) {
        bool ok = lane < THREADS / 32;
        d_abs = ok ? sh_a[lane] : 0.0;
        d_sq  = ok ? sh_s[lane] : 0.0;
        ca    = ok ? sh_ca[lane] : 0u;
        cs    = ok ? sh_cs[lane] : 0u;
        d_abs = wred_d(d_abs); d_sq = wred_d(d_sq);
        ca = wred_u(ca); cs = wred_u(cs);
        if (lane == 0) {
            atomicAdd(&g_thr_abs, d_abs);
            atomicAdd(&g_thr_sq,  d_sq);
            atomicAdd(&g_cnt_abs, (unsigned long long)ca);
            atomicAdd(&g_cnt_sq,  (unsigned long long)cs);
        }
    }
}

// ---------------- finalize: pure scalar work ----------------
__global__ void final_kernel(float* __restrict__ out) {
    double mae = g_sum_abs / (double)N_ELEMS;
    double mse = g_sum_sq  / (double)N_ELEMS;
    double mae_thr = (g_cnt_abs > 0) ? g_thr_abs / (double)g_cnt_abs : 0.0;
    double mse_thr = (g_cnt_sq  > 0) ? g_thr_sq  / (double)g_cnt_sq  : 0.0;
    double total = 0.5 * (0.5 * mae_thr + 0.5 * mse_thr)
                 + 0.5 * (0.5 * mae     + 0.5 * mse);
    out[0] = (float)total;
}

extern "C" void kernel_launch(void* const* d_in, const int* in_sizes, int n_in,
                              void* d_out, int out_size) {
    const float4* a = (const float4*)d_in[0];
    const float4* b = (const float4*)d_in[1];
    float* out = (float*)d_out;

    zero_kernel<<<1, 1>>>();
    pass1_kernel<<<BLOCKS, THREADS>>>(a, b);
    pass2_kernel<<<BLOCKS, THREADS>>>();
    final_kernel<<<1, 1>>>(out);
}

// round 5
// speedup vs baseline: 1.8462x; 1.0158x over previous
#include <cuda_runtime.h>
#include <cuda_fp16.h>

// total_loss = 0.5*(0.5*mae_thr + 0.5*mse_thr) + 0.5*(0.5*mae + 0.5*mse)
// N = 32*3*512*512 = 25165824 fp32 per input.

#define N_ELEMS   25165824
#define BLOCKS    1184         // 148 SMs * 8
#define THREADS   256
#define TOT       (BLOCKS * THREADS)   // 303104
#define P1_ITERS  20           // N/4  = TOT*20 + 229376
#define P1_REM    229376
#define P2_ITERS  10           // N/8  = TOT*10 + 114688
#define P2_REM    114688

// ---- static device scratch (no runtime allocation allowed) ----
__device__ __half  g_absdiff[N_ELEMS];          // 50.3 MB |d| in fp16
__device__ double  g_sum_abs, g_sum_sq;         // pass1 totals (atomics)
__device__ double  g_thr_abs, g_thr_sq;         // pass2 totals (atomics)
__device__ unsigned long long g_cnt_abs, g_cnt_sq;
__device__ unsigned g_done;                     // pass2 block-arrival counter

__device__ __forceinline__ double wred_d(double v) {
    #pragma unroll
    for (int o = 16; o > 0; o >>= 1) v += __shfl_down_sync(0xFFFFFFFFu, v, o);
    return v;
}
__device__ __forceinline__ unsigned wred_u(unsigned v) {
    #pragma unroll
    for (int o = 16; o > 0; o >>= 1) v += __shfl_down_sync(0xFFFFFFFFu, v, o);
    return v;
}

__global__ void zero_kernel() {
    g_sum_abs = 0.0; g_sum_sq = 0.0;
    g_thr_abs = 0.0; g_thr_sq = 0.0;
    g_cnt_abs = 0ULL; g_cnt_sq = 0ULL;
    g_done = 0u;
}

// ---------------- Pass 1: sums of |d|, d^2 ; write |d| as fp16 ----------------
__global__ void __launch_bounds__(THREADS)
pass1_kernel(const float4* __restrict__ a, const float4* __restrict__ b) {
    const int tid = blockIdx.x * THREADS + threadIdx.x;
    uint2* __restrict__ outp = reinterpret_cast<uint2*>(g_absdiff);  // 4 halfs per uint2
    double d_abs = 0.0, d_sq = 0.0;

    #pragma unroll
    for (int outer = 0; outer < 5; outer++) {
        const int base = tid + outer * 4 * TOT;
        float4 xa[4], xb[4];
        #pragma unroll
        for (int k = 0; k < 4; k++) {
            xa[k] = __ldcs(a + base + k * TOT);   // streaming: evict-first
            xb[k] = __ldcs(b + base + k * TOT);
        }
        float fa = 0.0f, fs = 0.0f;
        #pragma unroll
        for (int k = 0; k < 4; k++) {
            float d0 = xa[k].x - xb[k].x, d1 = xa[k].y - xb[k].y;
            float d2 = xa[k].z - xb[k].z, d3 = xa[k].w - xb[k].w;
            float a0 = fabsf(d0), a1 = fabsf(d1), a2 = fabsf(d2), a3 = fabsf(d3);
            fa += (a0 + a1) + (a2 + a3);
            fs += (d0*d0 + d1*d1) + (d2*d2 + d3*d3);
            __half2 h01 = __floats2half2_rn(a0, a1);
            __half2 h23 = __floats2half2_rn(a2, a3);
            uint2 pk;
            pk.x = reinterpret_cast<unsigned&>(h01);
            pk.y = reinterpret_cast<unsigned&>(h23);
            outp[base + k * TOT] = pk;            // default policy: keep in L2
        }
        d_abs += (double)fa; d_sq += (double)fs;
    }
    if (tid < P1_REM) {
        const int idx = tid + P1_ITERS * TOT;
        float4 xa = __ldcs(a + idx), xb = __ldcs(b + idx);
        float d0 = xa.x - xb.x, d1 = xa.y - xb.y, d2 = xa.z - xb.z, d3 = xa.w - xb.w;
        float a0 = fabsf(d0), a1 = fabsf(d1), a2 = fabsf(d2), a3 = fabsf(d3);
        d_abs += (double)((a0 + a1) + (a2 + a3));
        d_sq  += (double)((d0*d0 + d1*d1) + (d2*d2 + d3*d3));
        __half2 h01 = __floats2half2_rn(a0, a1);
        __half2 h23 = __floats2half2_rn(a2, a3);
        uint2 pk;
        pk.x = reinterpret_cast<unsigned&>(h01);
        pk.y = reinterpret_cast<unsigned&>(h23);
        outp[idx] = pk;
    }

    // block reduce (double) -> 2 atomics per block
    __shared__ double sh_a[THREADS / 32], sh_s[THREADS / 32];
    int lane = threadIdx.x & 31, wid = threadIdx.x >> 5;
    d_abs = wred_d(d_abs); d_sq = wred_d(d_sq);
    if (lane == 0) { sh_a[wid] = d_abs; sh_s[wid] = d_sq; }
    __syncthreads();
    if (wid == 0) {
        bool ok = lane < THREADS / 32;
        d_abs = ok ? sh_a[lane] : 0.0;
        d_sq  = ok ? sh_s[lane] : 0.0;
        d_abs = wred_d(d_abs); d_sq = wred_d(d_sq);
        if (lane == 0) {
            atomicAdd(&g_sum_abs, d_abs);
            atomicAdd(&g_sum_sq,  d_sq);
        }
    }
}

// ---------------- Pass 2: thresholded sums + counts; last block finalizes ----------------
__global__ void __launch_bounds__(THREADS)
pass2_kernel(float* __restrict__ out) {
    // thresholds from pass1 totals (stream-ordered, visible at launch)
    const double sum_abs = g_sum_abs;
    const double sum_sq  = g_sum_sq;
    const float mae_t = (float)(sum_abs * (1.0 / (double)N_ELEMS));
    const float mse_t = (float)(sum_sq  * (1.0 / (double)N_ELEMS));
    const int tid = blockIdx.x * THREADS + threadIdx.x;
    const uint4* __restrict__ in = reinterpret_cast<const uint4*>(g_absdiff); // 8 halfs
    double d_abs = 0.0, d_sq = 0.0;
    unsigned ca = 0, cs = 0;

    #pragma unroll
    for (int outer = 0; outer < 2; outer++) {
        const int base = tid + outer * 5 * TOT;
        uint4 v[5];
        #pragma unroll
        for (int k = 0; k < 5; k++) v[k] = __ldcs(in + base + k * TOT);
        float fa = 0.0f, fs = 0.0f;
        #pragma unroll
        for (int k = 0; k < 5; k++) {
            unsigned w[4] = {v[k].x, v[k].y, v[k].z, v[k].w};
            #pragma unroll
            for (int j = 0; j < 4; j++) {
                __half2 h = reinterpret_cast<__half2&>(w[j]);
                float2 f = __half22float2(h);
                float vv0 = f.x * f.x, vv1 = f.y * f.y;
                if (f.x >= mae_t) { fa += f.x; ca++; }
                if (f.y >= mae_t) { fa += f.y; ca++; }
                if (vv0 >= mse_t) { fs += vv0; cs++; }
                if (vv1 >= mse_t) { fs += vv1; cs++; }
            }
        }
        d_abs += (double)fa; d_sq += (double)fs;
    }
    if (tid < P2_REM) {
        uint4 v = __ldcs(in + tid + P2_ITERS * TOT);
        unsigned w[4] = {v.x, v.y, v.z, v.w};
        float fa = 0.0f, fs = 0.0f;
        #pragma unroll
        for (int j = 0; j < 4; j++) {
            __half2 h = reinterpret_cast<__half2&>(w[j]);
            float2 f = __half22float2(h);
            float vv0 = f.x * f.x, vv1 = f.y * f.y;
            if (f.x >= mae_t) { fa += f.x; ca++; }
            if (f.y >= mae_t) { fa += f.y; ca++; }
            if (vv0 >= mse_t) { fs += vv0; cs++; }
            if (vv1 >= mse_t) { fs += vv1; cs++; }
        }
        d_abs += (double)fa; d_sq += (double)fs;
    }

    __shared__ double   sh_a[THREADS / 32], sh_s[THREADS / 32];
    __shared__ unsigned sh_ca[THREADS / 32], sh_cs[THREADS / 32];
    __shared__ bool     sh_last;
    int lane = threadIdx.x & 31, wid = threadIdx.x >> 5;
    d_abs = wred_d(d_abs); d_sq = wred_d(d_sq);
    ca = wred_u(ca); cs = wred_u(cs);
    if (lane == 0) { sh_a[wid] = d_abs; sh_s[wid] = d_sq; sh_ca[wid] = ca; sh_cs[wid] = cs; }
    __syncthreads();
    if (wid == 0) {
        bool ok = lane < THREADS / 32;
        d_abs = ok ? sh_a[lane] : 0.0;
        d_sq  = ok ? sh_s[lane] : 0.0;
        ca    = ok ? sh_ca[lane] : 0u;
        cs    = ok ? sh_cs[lane] : 0u;
        d_abs = wred_d(d_abs); d_sq = wred_d(d_sq);
        ca = wred_u(ca); cs = wred_u(cs);
        if (lane == 0) {
            atomicAdd(&g_thr_abs, d_abs);
            atomicAdd(&g_thr_sq,  d_sq);
            atomicAdd(&g_cnt_abs, (unsigned long long)ca);
            atomicAdd(&g_cnt_sq,  (unsigned long long)cs);
            __threadfence();
            unsigned prev = atomicAdd(&g_done, 1u);
            sh_last = (prev == BLOCKS - 1);
        }
    }
    __syncthreads();

    // last block to finish: compute the final scalar
    if (sh_last && threadIdx.x == 0) {
        __threadfence();
        double va = *((volatile double*)&g_thr_abs);
        double vs = *((volatile double*)&g_thr_sq);
        unsigned long long na = *((volatile unsigned long long*)&g_cnt_abs);
        unsigned long long ns = *((volatile unsigned long long*)&g_cnt_sq);
        double mae = sum_abs * (1.0 / (double)N_ELEMS);
        double mse = sum_sq  * (1.0 / (double)N_ELEMS);
        double mae_thr = (na > 0) ? va / (double)na : 0.0;
        double mse_thr = (ns > 0) ? vs / (double)ns : 0.0;
        double total = 0.5 * (0.5 * mae_thr + 0.5 * mse_thr)
                     + 0.5 * (0.5 * mae     + 0.5 * mse);
        out[0] = (float)total;
    }
}

extern "C" void kernel_launch(void* const* d_in, const int* in_sizes, int n_in,
                              void* d_out, int out_size) {
    const float4* a = (const float4*)d_in[0];
    const float4* b = (const float4*)d_in[1];
    float* out = (float*)d_out;

    zero_kernel<<<1, 1>>>();
    pass1_kernel<<<BLOCKS, THREADS>>>(a, b);
    pass2_kernel<<<BLOCKS, THREADS>>>(out);
}

// round 6
// speedup vs baseline: 2.1454x; 1.1621x over previous
#include <cuda_runtime.h>
#include <cuda_fp16.h>

// total_loss = 0.5*(0.5*mae_thr + 0.5*mse_thr) + 0.5*(0.5*mae + 0.5*mse)
// N = 32*3*512*512 = 25165824 fp32 per input.

#define N_ELEMS   25165824
#define BLOCKS    1184         // 148 SMs * 8
#define THREADS   256
#define TOT       (BLOCKS * THREADS)   // 303104
// 8-element groups: N/8 = 3145728 = TOT*10 + 114688
#define G_ITERS   10
#define G_REM     114688

// ---- static device scratch (no runtime allocation allowed) ----
__device__ __half  g_absdiff[N_ELEMS];          // 50.3 MB |d| in fp16
__device__ double  g_sum_abs, g_sum_sq;         // pass1 totals (atomics)
__device__ double  g_thr_abs, g_thr_sq;         // pass2 totals (atomics)
__device__ unsigned long long g_cnt_abs, g_cnt_sq;
__device__ unsigned g_done;                     // pass2 block-arrival counter

__device__ __forceinline__ double wred_d(double v) {
    #pragma unroll
    for (int o = 16; o > 0; o >>= 1) v += __shfl_down_sync(0xFFFFFFFFu, v, o);
    return v;
}
__device__ __forceinline__ float wred_f(float v) {
    #pragma unroll
    for (int o = 16; o > 0; o >>= 1) v += __shfl_down_sync(0xFFFFFFFFu, v, o);
    return v;
}

// ---------------- Pass 1: sums of |d|, d^2 ; write |d| as fp16 (uint4) ----------------
__device__ __forceinline__ void p1_body(const float4* __restrict__ a,
                                        const float4* __restrict__ b,
                                        uint4* __restrict__ outp,
                                        int g, float& fa, float& fs) {
    float4 x0 = __ldcs(a + 2 * g), x1 = __ldcs(a + 2 * g + 1);
    float4 y0 = __ldcs(b + 2 * g), y1 = __ldcs(b + 2 * g + 1);
    float d0 = x0.x - y0.x, d1 = x0.y - y0.y, d2 = x0.z - y0.z, d3 = x0.w - y0.w;
    float d4 = x1.x - y1.x, d5 = x1.y - y1.y, d6 = x1.z - y1.z, d7 = x1.w - y1.w;
    float a0 = fabsf(d0), a1 = fabsf(d1), a2 = fabsf(d2), a3 = fabsf(d3);
    float a4 = fabsf(d4), a5 = fabsf(d5), a6 = fabsf(d6), a7 = fabsf(d7);
    fa += ((a0 + a1) + (a2 + a3)) + ((a4 + a5) + (a6 + a7));
    fs += ((d0*d0 + d1*d1) + (d2*d2 + d3*d3)) + ((d4*d4 + d5*d5) + (d6*d6 + d7*d7));
    __half2 h01 = __floats2half2_rn(a0, a1);
    __half2 h23 = __floats2half2_rn(a2, a3);
    __half2 h45 = __floats2half2_rn(a4, a5);
    __half2 h67 = __floats2half2_rn(a6, a7);
    uint4 pk;
    pk.x = reinterpret_cast<unsigned&>(h01);
    pk.y = reinterpret_cast<unsigned&>(h23);
    pk.z = reinterpret_cast<unsigned&>(h45);
    pk.w = reinterpret_cast<unsigned&>(h67);
    outp[g] = pk;
}

__global__ void __launch_bounds__(THREADS)
pass1_kernel(const float4* __restrict__ a, const float4* __restrict__ b) {
    const int tid = blockIdx.x * THREADS + threadIdx.x;
    uint4* __restrict__ outp = reinterpret_cast<uint4*>(g_absdiff);
    double d_abs = 0.0, d_sq = 0.0;

    #pragma unroll
    for (int outer = 0; outer < 2; outer++) {
        float fa = 0.0f, fs = 0.0f;
        #pragma unroll
        for (int k = 0; k < 5; k++) {
            p1_body(a, b, outp, tid + (outer * 5 + k) * TOT, fa, fs);
        }
        d_abs += (double)fa; d_sq += (double)fs;
    }
    if (tid < G_REM) {
        float fa = 0.0f, fs = 0.0f;
        p1_body(a, b, outp, tid + G_ITERS * TOT, fa, fs);
        d_abs += (double)fa; d_sq += (double)fs;
    }

    __shared__ double sh_a[THREADS / 32], sh_s[THREADS / 32];
    int lane = threadIdx.x & 31, wid = threadIdx.x >> 5;
    d_abs = wred_d(d_abs); d_sq = wred_d(d_sq);
    if (lane == 0) { sh_a[wid] = d_abs; sh_s[wid] = d_sq; }
    __syncthreads();
    if (wid == 0) {
        bool ok = lane < THREADS / 32;
        d_abs = ok ? sh_a[lane] : 0.0;
        d_sq  = ok ? sh_s[lane] : 0.0;
        d_abs = wred_d(d_abs); d_sq = wred_d(d_sq);
        if (lane == 0) {
            atomicAdd(&g_sum_abs, d_abs);
            atomicAdd(&g_sum_sq,  d_sq);
        }
    }
}

// ---------------- Pass 2: half2 SIMD thresholding; last block finalizes + resets ----------------
__global__ void __launch_bounds__(THREADS)
pass2_kernel(float* __restrict__ out) {
    const double sum_abs = g_sum_abs;
    const double sum_sq  = g_sum_sq;
    const float mae_f = (float)(sum_abs * (1.0 / (double)N_ELEMS));
    const float mse_f = (float)(sum_sq  * (1.0 / (double)N_ELEMS));
    // both tests are thresholds on |d|: |d| >= mae  and |d| >= sqrt(mse)
    const __half2 t1 = __half2half2(__float2half_ru(mae_f));
    const __half2 t2 = __half2half2(__float2half_ru(sqrtf(mse_f)));

    const int tid = blockIdx.x * THREADS + threadIdx.x;
    const uint4* __restrict__ in = reinterpret_cast<const uint4*>(g_absdiff);

    float s1 = 0.0f, s2 = 0.0f;                 // fp32 totals (flushed)
    __half2 c1 = __float2half2_rn(0.0f);        // counts stay fp16 (exact, <=44/lane)
    __half2 c2 = __float2half2_rn(0.0f);

    #pragma unroll
    for (int outer = 0; outer < 2; outer++) {
        __half2 s1h = __float2half2_rn(0.0f);   // <=20 adds/lane before flush
        __half2 s2h = __float2half2_rn(0.0f);
        #pragma unroll
        for (int k = 0; k < 5; k++) {
            uint4 v = __ldcs(in + tid + (outer * 5 + k) * TOT);
            unsigned w[4] = {v.x, v.y, v.z, v.w};
            #pragma unroll
            for (int j = 0; j < 4; j++) {
                __half2 h = reinterpret_cast<__half2&>(w[j]);
                __half2 m1 = __hge2(h, t1);     // 1.0 / 0.0 per lane
                __half2 m2 = __hge2(h, t2);
                s1h = __hfma2(h, m1, s1h);      // masked |d|
                c1  = __hadd2(c1, m1);
                c2  = __hadd2(c2, m2);
                __half2 hm = __hmul2(h, m2);
                s2h = __hfma2(hm, h, s2h);      // masked d^2
            }
        }
        float2 f1 = __half22float2(s1h);
        float2 f2 = __half22float2(s2h);
        s1 += f1.x + f1.y;
        s2 += f2.x + f2.y;
    }
    if (tid < G_REM) {
        uint4 v = __ldcs(in + tid + G_ITERS * TOT);
        unsigned w[4] = {v.x, v.y, v.z, v.w};
        __half2 s1h = __float2half2_rn(0.0f);
        __half2 s2h = __float2half2_rn(0.0f);
        #pragma unroll
        for (int j = 0; j < 4; j++) {
            __half2 h = reinterpret_cast<__half2&>(w[j]);
            __half2 m1 = __hge2(h, t1);
            __half2 m2 = __hge2(h, t2);
            s1h = __hfma2(h, m1, s1h);
            c1  = __hadd2(c1, m1);
            c2  = __hadd2(c2, m2);
            __half2 hm = __hmul2(h, m2);
            s2h = __hfma2(hm, h, s2h);
        }
        float2 f1 = __half22float2(s1h);
        float2 f2 = __half22float2(s2h);
        s1 += f1.x + f1.y;
        s2 += f2.x + f2.y;
    }

    float2 c1f = __half22float2(c1);
    float2 c2f = __half22float2(c2);
    float cnt1 = c1f.x + c1f.y;
    float cnt2 = c2f.x + c2f.y;

    // block reduce in fp32 (block partial sums well within fp32 exactness/precision)
    __shared__ float sh_a[THREADS / 32], sh_s[THREADS / 32];
    __shared__ float sh_ca[THREADS / 32], sh_cs[THREADS / 32];
    __shared__ bool  sh_last;
    int lane = threadIdx.x & 31, wid = threadIdx.x >> 5;
    s1 = wred_f(s1); s2 = wred_f(s2);
    cnt1 = wred_f(cnt1); cnt2 = wred_f(cnt2);
    if (lane == 0) { sh_a[wid] = s1; sh_s[wid] = s2; sh_ca[wid] = cnt1; sh_cs[wid] = cnt2; }
    __syncthreads();
    if (wid == 0) {
        bool ok = lane < THREADS / 32;
        s1   = ok ? sh_a[lane]  : 0.0f;
        s2   = ok ? sh_s[lane]  : 0.0f;
        cnt1 = ok ? sh_ca[lane] : 0.0f;
        cnt2 = ok ? sh_cs[lane] : 0.0f;
        s1 = wred_f(s1); s2 = wred_f(s2);
        cnt1 = wred_f(cnt1); cnt2 = wred_f(cnt2);
        if (lane == 0) {
            atomicAdd(&g_thr_abs, (double)s1);
            atomicAdd(&g_thr_sq,  (double)s2);
            atomicAdd(&g_cnt_abs, (unsigned long long)(long long)cnt1);
            atomicAdd(&g_cnt_sq,  (unsigned long long)(long long)cnt2);
            __threadfence();
            unsigned prev = atomicAdd(&g_done, 1u);
            sh_last = (prev == BLOCKS - 1);
        }
    }
    __syncthreads();

    // last block: finalize and reset accumulators for the next graph replay
    if (sh_last && threadIdx.x == 0) {
        __threadfence();
        double va = *((volatile double*)&g_thr_abs);
        double vs = *((volatile double*)&g_thr_sq);
        unsigned long long na = *((volatile unsigned long long*)&g_cnt_abs);
        unsigned long long ns = *((volatile unsigned long long*)&g_cnt_sq);
        double mae = sum_abs * (1.0 / (double)N_ELEMS);
        double mse = sum_sq  * (1.0 / (double)N_ELEMS);
        double mae_thr = (na > 0) ? va / (double)na : 0.0;
        double mse_thr = (ns > 0) ? vs / (double)ns : 0.0;
        double total = 0.5 * (0.5 * mae_thr + 0.5 * mse_thr)
                     + 0.5 * (0.5 * mae     + 0.5 * mse);
        out[0] = (float)total;
        // reset for next replay
        g_sum_abs = 0.0; g_sum_sq = 0.0;
        g_thr_abs = 0.0; g_thr_sq = 0.0;
        g_cnt_abs = 0ULL; g_cnt_sq = 0ULL;
        g_done = 0u;
    }
}

extern "C" void kernel_launch(void* const* d_in, const int* in_sizes, int n_in,
                              void* d_out, int out_size) {
    const float4* a = (const float4*)d_in[0];
    const float4* b = (const float4*)d_in[1];
    float* out = (float*)d_out;

    pass1_kernel<<<BLOCKS, THREADS>>>(a, b);
    pass2_kernel<<<BLOCKS, THREADS>>>(out);
}

// round 8
// speedup vs baseline: 2.6774x; 1.2480x over previous
#include <cuda_runtime.h>
#include <cuda_fp16.h>

// total_loss = 0.5*(0.5*mae_thr + 0.5*mse_thr) + 0.5*(0.5*mae + 0.5*mse)
// N = 32*3*512*512 = 25165824 fp32 per input.

#define N_ELEMS   25165824
#define BLOCKS    592          // 148 SMs * 4  (co-resident for grid sync)
#define THREADS   256
#define TOT       (BLOCKS * THREADS)   // 151552
// 8-element groups: N/8 = 3145728 = TOT*20 + 114688
#define G_ITERS   20
#define G_REM     114688

// ---- static device scratch (no runtime allocation allowed) ----
__device__ __half  g_absdiff[N_ELEMS];          // 50.3 MB |d| in fp16 (L2 evict_last)
__device__ double  g_sum_abs, g_sum_sq;         // phase1 totals
__device__ double  g_thr_abs, g_thr_sq;         // phase2 totals
__device__ unsigned long long g_cnt_abs, g_cnt_sq;
__device__ unsigned g_done1, g_done2;           // grid-sync counters

__device__ __forceinline__ double wred_d(double v) {
    #pragma unroll
    for (int o = 16; o > 0; o >>= 1) v += __shfl_down_sync(0xFFFFFFFFu, v, o);
    return v;
}
__device__ __forceinline__ float wred_f(float v) {
    #pragma unroll
    for (int o = 16; o > 0; o >>= 1) v += __shfl_down_sync(0xFFFFFFFFu, v, o);
    return v;
}
__device__ __forceinline__ unsigned ld_acquire_u32(const unsigned* p) {
    unsigned v;
    asm volatile("ld.global.acquire.gpu.u32 %0, [%1];" : "=r"(v) : "l"(p));
    return v;
}
__device__ __forceinline__ void st_evict_last(uint4* p, uint4 v, unsigned long long pol) {
    asm volatile("st.global.L2::cache_hint.v4.b32 [%0], {%1,%2,%3,%4}, %5;"
                 :: "l"(p), "r"(v.x), "r"(v.y), "r"(v.z), "r"(v.w), "l"(pol)
                 : "memory");
}
__device__ __forceinline__ void discard_line(const void* p) {
    asm volatile("discard.global.L2 [%0], 128;" :: "l"(p) : "memory");
}

// ---- phase 1 body: one 8-elem group ----
__device__ __forceinline__ void p1_body(const float4* __restrict__ a,
                                        const float4* __restrict__ b,
                                        uint4* __restrict__ outp,
                                        int g, float& fa, float& fs,
                                        unsigned long long pol) {
    float4 x0 = __ldcs(a + 2 * g), x1 = __ldcs(a + 2 * g + 1);
    float4 y0 = __ldcs(b + 2 * g), y1 = __ldcs(b + 2 * g + 1);
    float d0 = x0.x - y0.x, d1 = x0.y - y0.y, d2 = x0.z - y0.z, d3 = x0.w - y0.w;
    float d4 = x1.x - y1.x, d5 = x1.y - y1.y, d6 = x1.z - y1.z, d7 = x1.w - y1.w;
    float a0 = fabsf(d0), a1 = fabsf(d1), a2 = fabsf(d2), a3 = fabsf(d3);
    float a4 = fabsf(d4), a5 = fabsf(d5), a6 = fabsf(d6), a7 = fabsf(d7);
    fa += ((a0 + a1) + (a2 + a3)) + ((a4 + a5) + (a6 + a7));
    fs += ((d0*d0 + d1*d1) + (d2*d2 + d3*d3)) + ((d4*d4 + d5*d5) + (d6*d6 + d7*d7));
    __half2 h01 = __floats2half2_rn(a0, a1);
    __half2 h23 = __floats2half2_rn(a2, a3);
    __half2 h45 = __floats2half2_rn(a4, a5);
    __half2 h67 = __floats2half2_rn(a6, a7);
    uint4 pk;
    pk.x = reinterpret_cast<unsigned&>(h01);
    pk.y = reinterpret_cast<unsigned&>(h23);
    pk.z = reinterpret_cast<unsigned&>(h45);
    pk.w = reinterpret_cast<unsigned&>(h67);
    st_evict_last(outp + g, pk, pol);
}

// ---- phase 2 body: one uint4 (8 halfs) ----
__device__ __forceinline__ void p2_body(uint4 v, __half2 t1, __half2 t2,
                                        __half2& s1h, __half2& s2h,
                                        __half2& c1, __half2& c2) {
    unsigned w[4] = {v.x, v.y, v.z, v.w};
    #pragma unroll
    for (int j = 0; j < 4; j++) {
        __half2 h = reinterpret_cast<__half2&>(w[j]);
        __half2 m1 = __hge2(h, t1);
        __half2 m2 = __hge2(h, t2);
        s1h = __hfma2(h, m1, s1h);
        c1  = __hadd2(c1, m1);
        c2  = __hadd2(c2, m2);
        __half2 hm = __hmul2(h, m2);
        s2h = __hfma2(hm, h, s2h);
    }
}

__global__ void __launch_bounds__(THREADS, 4)
fused_kernel(const float4* __restrict__ a, const float4* __restrict__ b,
             float* __restrict__ out) {
    const int tid = blockIdx.x * THREADS + threadIdx.x;
    const int lane = threadIdx.x & 31, wid = threadIdx.x >> 5;

    unsigned long long pol;
    asm volatile("createpolicy.fractional.L2::evict_last.b64 %0, 1.0;" : "=l"(pol));

    uint4* __restrict__ outp = reinterpret_cast<uint4*>(g_absdiff);

    // ================= Phase 1 =================
    double d_abs = 0.0, d_sq = 0.0;
    #pragma unroll
    for (int outer = 0; outer < 4; outer++) {
        float fa = 0.0f, fs = 0.0f;
        #pragma unroll
        for (int k = 0; k < 5; k++)
            p1_body(a, b, outp, tid + (outer * 5 + k) * TOT, fa, fs, pol);
        d_abs += (double)fa; d_sq += (double)fs;
    }
    if (tid < G_REM) {
        float fa = 0.0f, fs = 0.0f;
        p1_body(a, b, outp, tid + G_ITERS * TOT, fa, fs, pol);
        d_abs += (double)fa; d_sq += (double)fs;
    }

    {   // block reduce -> global atomics -> arrive
        __shared__ double sh_a[THREADS / 32], sh_s[THREADS / 32];
        d_abs = wred_d(d_abs); d_sq = wred_d(d_sq);
        if (lane == 0) { sh_a[wid] = d_abs; sh_s[wid] = d_sq; }
        __syncthreads();
        if (wid == 0) {
            bool ok = lane < THREADS / 32;
            d_abs = ok ? sh_a[lane] : 0.0;
            d_sq  = ok ? sh_s[lane] : 0.0;
            d_abs = wred_d(d_abs); d_sq = wred_d(d_sq);
            if (lane == 0) {
                atomicAdd(&g_sum_abs, d_abs);
                atomicAdd(&g_sum_sq,  d_sq);
                __threadfence();
                atomicAdd(&g_done1, 1u);
            }
        }
    }

    // ================= grid-wide sync =================
    if (threadIdx.x == 0) {
        while (ld_acquire_u32(&g_done1) < BLOCKS) __nanosleep(64);
    }
    __syncthreads();

    // ================= Phase 2 =================
    const double sum_abs = *((volatile double*)&g_sum_abs);
    const double sum_sq  = *((volatile double*)&g_sum_sq);
    const float mae_f = (float)(sum_abs * (1.0 / (double)N_ELEMS));
    const float mse_f = (float)(sum_sq  * (1.0 / (double)N_ELEMS));
    // both tests are thresholds on |d|: |d| >= mae  and |d| >= sqrt(mse)
    const __half2 t1 = __half2half2(__float2half_ru(mae_f));
    const __half2 t2 = __half2half2(__float2half_ru(sqrtf(mse_f)));

    const uint4* __restrict__ in = reinterpret_cast<const uint4*>(g_absdiff);

    float s1 = 0.0f, s2 = 0.0f;
    __half2 c1 = __float2half2_rn(0.0f);   // exact integer counts (<=84/lane)
    __half2 c2 = __float2half2_rn(0.0f);

    #pragma unroll
    for (int outer = 0; outer < 4; outer++) {
        uint4 v[5];
        #pragma unroll
        for (int k = 0; k < 5; k++) v[k] = __ldcs(in + tid + (outer * 5 + k) * TOT);
        __half2 s1h = __float2half2_rn(0.0f);
        __half2 s2h = __float2half2_rn(0.0f);
        #pragma unroll
        for (int k = 0; k < 5; k++) p2_body(v[k], t1, t2, s1h, s2h, c1, c2);
        float2 f1 = __half22float2(s1h);
        float2 f2 = __half22float2(s2h);
        s1 += f1.x + f1.y;
        s2 += f2.x + f2.y;
    }
    if (tid < G_REM) {
        uint4 v = __ldcs(in + tid + G_ITERS * TOT);
        __half2 s1h = __float2half2_rn(0.0f);
        __half2 s2h = __float2half2_rn(0.0f);
        p2_body(v, t1, t2, s1h, s2h, c1, c2);
        float2 f1 = __half22float2(s1h);
        float2 f2 = __half22float2(s2h);
        s1 += f1.x + f1.y;
        s2 += f2.x + f2.y;
    }

    float2 c1f = __half22float2(c1);
    float2 c2f = __half22float2(c2);
    float cnt1 = c1f.x + c1f.y;
    float cnt2 = c2f.x + c2f.y;

    __shared__ float sh_a[THREADS / 32], sh_s[THREADS / 32];
    __shared__ float sh_ca[THREADS / 32], sh_cs[THREADS / 32];
    __shared__ bool  sh_last;
    s1 = wred_f(s1); s2 = wred_f(s2);
    cnt1 = wred_f(cnt1); cnt2 = wred_f(cnt2);
    if (lane == 0) { sh_a[wid] = s1; sh_s[wid] = s2; sh_ca[wid] = cnt1; sh_cs[wid] = cnt2; }
    __syncthreads();   // all block loads consumed beyond this point

    // discard this block's scratch lines (dirty, never needed again -> no DRAM writeback)
    if ((threadIdx.x & 7) == 0) {
        #pragma unroll
        for (int k = 0; k < G_ITERS; k++) discard_line(in + tid + k * TOT);
        if (tid < G_REM) discard_line(in + tid + G_ITERS * TOT);
    }

    if (wid == 0) {
        bool ok = lane < THREADS / 32;
        s1   = ok ? sh_a[lane]  : 0.0f;
        s2   = ok ? sh_s[lane]  : 0.0f;
        cnt1 = ok ? sh_ca[lane] : 0.0f;
        cnt2 = ok ? sh_cs[lane] : 0.0f;
        s1 = wred_f(s1); s2 = wred_f(s2);
        cnt1 = wred_f(cnt1); cnt2 = wred_f(cnt2);
        if (lane == 0) {
            atomicAdd(&g_thr_abs, (double)s1);
            atomicAdd(&g_thr_sq,  (double)s2);
            atomicAdd(&g_cnt_abs, (unsigned long long)(long long)cnt1);
            atomicAdd(&g_cnt_sq,  (unsigned long long)(long long)cnt2);
            __threadfence();
            unsigned prev = atomicAdd(&g_done2, 1u);
            sh_last = (prev == BLOCKS - 1);
        }
    }
    __syncthreads();

    // last block: finalize, write result, reset state for the next graph replay
    if (sh_last && threadIdx.x == 0) {
        __threadfence();
        double va = *((volatile double*)&g_thr_abs);
        double vs = *((volatile double*)&g_thr_sq);
        unsigned long long na = *((volatile unsigned long long*)&g_cnt_abs);
        unsigned long long ns = *((volatile unsigned long long*)&g_cnt_sq);
        double mae = sum_abs * (1.0 / (double)N_ELEMS);
        double mse = sum_sq  * (1.0 / (double)N_ELEMS);
        double mae_thr = (na > 0) ? va / (double)na : 0.0;
        double mse_thr = (ns > 0) ? vs / (double)ns : 0.0;
        double total = 0.5 * (0.5 * mae_thr + 0.5 * mse_thr)
                     + 0.5 * (0.5 * mae     + 0.5 * mse);
        out[0] = (float)total;
        g_sum_abs = 0.0; g_sum_sq = 0.0;
        g_thr_abs = 0.0; g_thr_sq = 0.0;
        g_cnt_abs = 0ULL; g_cnt_sq = 0ULL;
        g_done1 = 0u; g_done2 = 0u;
    }
}

extern "C" void kernel_launch(void* const* d_in, const int* in_sizes, int n_in,
                              void* d_out, int out_size) {
    const float4* a = (const float4*)d_in[0];
    const float4* b = (const float4*)d_in[1];
    float* out = (float*)d_out;

    fused_kernel<<<BLOCKS, THREADS>>>(a, b, out);
}